// round 16
// baseline (speedup 1.0000x reference)
#include <cuda_runtime.h>
#include <cuda_fp16.h>
#include <cuda_pipeline.h>
#include <mma.h>
#include <cstdint>

using namespace nvcuda;

#define NN 100000
#define NE 1600000
#define SCAN_B 1024
#define NBLK ((NN + SCAN_B - 1) / SCAN_B)   // 98

// ---------------- scratch (device globals; no allocation allowed) ----------------
__device__ __align__(16) unsigned g_aggrP[(size_t)NN * 128];  // packed (fp16 hi | fp16 lo<<16); same bytes as fp32
__device__ __align__(16) float g_h[(size_t)NN * 128];
__device__ int g_deg[NN];                   // zeroed by scan right after read
__device__ int g_rowStart[NN + 1];
__device__ int g_cursor[NN];
__device__ int g_srcIdx[NE];
__device__ int g_part[NBLK];
__device__ int g_flag[NBLK];                // zeroed by k_count each call (replay-safe)
// fp16 weight images: [half][k 0..127][n 0..NP)
__device__ __align__(16) unsigned short g_Bimg1[2 * 128 * 136];  // layer1 NP=136
__device__ __align__(16) unsigned short g_Bimg2[2 * 128 * 72];   // layer2 NP=72

// split one float pair into packed fp16 hi and lo words (hi+lo ~exact to 2^-22)
__device__ __forceinline__ void split2h(float a, float b, uint32_t& h, uint32_t& l) {
    __half2 hb = __floats2half2_rn(a, b);
    float2 hf = __half22float2(hb);
    __half2 lb = __floats2half2_rn(a - hf.x, b - hf.y);
    h = *reinterpret_cast<uint32_t*>(&hb);
    l = *reinterpret_cast<uint32_t*>(&lb);
}

// ---------------- CSR build: count -> one-pass scan (decoupled lookback) -> fill ----------
__global__ void k_count(const int* __restrict__ edst) {
    int i = blockIdx.x * blockDim.x + threadIdx.x;
    if (i < NBLK) g_flag[i] = 0;            // reset lookback flags for this call/replay
    if (i < NE) atomicAdd(&g_deg[edst[i]], 1);
}
__global__ void __launch_bounds__(SCAN_B) k_scanOP() {
    __shared__ int s[SCAN_B];
    __shared__ int sbase;
    int t = threadIdx.x, b = blockIdx.x;
    int i = b * SCAN_B + t;
    int v = (i < NN) ? g_deg[i] : 0;
    if (i < NN) g_deg[i] = 0;               // restore invariant (only reader is this kernel)
    s[t] = v;
    __syncthreads();
#pragma unroll
    for (int off = 1; off < SCAN_B; off <<= 1) {
        int x = (t >= off) ? s[t - off] : 0;
        __syncthreads();
        s[t] += x;
        __syncthreads();
    }
    if (t == SCAN_B - 1) {                  // publish block total
        g_part[b] = s[SCAN_B - 1];
        __threadfence();
        atomicExch(&g_flag[b], 1);
    }
    if (t < 32) {                           // warp 0: parallel lookback over predecessors
        int sum = 0;
        for (int j = t; j < b; j += 32) {
            while (atomicAdd(&g_flag[j], 0) == 0) {}
            sum += atomicAdd(&g_part[j], 0);
        }
#pragma unroll
        for (int off = 16; off >= 1; off >>= 1)
            sum += __shfl_down_sync(0xFFFFFFFF, sum, off);
        if (t == 0) sbase = sum;
    }
    __syncthreads();
    if (i < NN) {
        int r = sbase + s[t] - v;           // exclusive prefix
        g_rowStart[i] = r;
        g_cursor[i] = r;
    }
    if (i == NN) g_rowStart[NN] = NE;       // i==NN occurs in the last block
}
__global__ void k_fill(const int* __restrict__ esrc, const int* __restrict__ edst) {
    int i = blockIdx.x * blockDim.x + threadIdx.x;
    if (i < NE) {
        int p = atomicAdd(&g_cursor[edst[i]], 1);
        g_srcIdx[p] = esrc[i];
    }
}

// ---------------- aggregation: warp per node, gather-max, emit PACKED hi/lo ----------------
__device__ __forceinline__ float4 max4(float4 a, float4 b) {
    return make_float4(fmaxf(a.x, b.x), fmaxf(a.y, b.y), fmaxf(a.z, b.z), fmaxf(a.w, b.w));
}
template<bool USE_H>
__global__ void __launch_bounds__(256) k_aggr(const float* __restrict__ xin) {
    int w = (blockIdx.x * blockDim.x + threadIdx.x) >> 5;
    if (w >= NN) return;
    int lane = threadIdx.x & 31;
    const float* feat = USE_H ? g_h : xin;
    int beg = g_rowStart[w];
    int end = g_rowStart[w + 1];
    const float NEG = __int_as_float(0xff800000);
    float4 m = make_float4(NEG, NEG, NEG, NEG);
    int e = beg;
    for (; e + 4 <= end; e += 4) {
        int s0 = g_srcIdx[e + 0], s1 = g_srcIdx[e + 1];
        int s2 = g_srcIdx[e + 2], s3 = g_srcIdx[e + 3];
        float4 v0 = *(const float4*)(feat + (size_t)s0 * 128 + lane * 4);
        float4 v1 = *(const float4*)(feat + (size_t)s1 * 128 + lane * 4);
        float4 v2 = *(const float4*)(feat + (size_t)s2 * 128 + lane * 4);
        float4 v3 = *(const float4*)(feat + (size_t)s3 * 128 + lane * 4);
        m = max4(m, max4(max4(v0, v1), max4(v2, v3)));
    }
    for (; e < end; e++) {
        float4 v0 = *(const float4*)(feat + (size_t)g_srcIdx[e] * 128 + lane * 4);
        m = max4(m, v0);
    }
    if (beg == end) m = make_float4(0.f, 0.f, 0.f, 0.f);
    // pack: per element (hi | lo<<16); same 16 bytes per lane as the old fp32 store
    uint32_t h01, l01, h23, l23;
    split2h(m.x, m.y, h01, l01);
    split2h(m.z, m.w, h23, l23);
    uint4 p;
    p.x = __byte_perm(h01, l01, 0x5410);    // (h0, l0)
    p.y = __byte_perm(h01, l01, 0x7632);    // (h1, l1)
    p.z = __byte_perm(h23, l23, 0x5410);
    p.w = __byte_perm(h23, l23, 0x7632);
    *(uint4*)(g_aggrP + (size_t)w * 128 + lane * 4) = p;
}

// ---------------- weight prep: single fp16 B[k][n] image per half ----------------
template<int COUT>
__global__ void k_prepB(const float* __restrict__ Wl, const float* __restrict__ Wr,
                        unsigned short* __restrict__ dst) {
    constexpr int NP = COUT + 8;
    int idx = blockIdx.x * blockDim.x + threadIdx.x;
    if (idx >= 2 * 128 * COUT) return;
    int half = idx / (128 * COUT);
    int rem = idx - half * 128 * COUT;
    int k = rem / COUT;
    int n = rem - k * COUT;
    float f = (half ? Wr : Wl)[k * COUT + n];
    __half hb = __float2half_rn(f);
    dst[((size_t)half * 128 + k) * NP + n] = *reinterpret_cast<unsigned short*>(&hb);
}

// ---------------- wmma fp16 2-term fused SAGE GEMM (R13 + packed-aggr staging) ----------
// CTA = 64 rows x COUT, 8 warps in 2(m) x 4(n), warp tile 32 x COUT/4. 3-4 CTAs/SM.
// Aggr half: pre-packed hi/lo, unpacked via byte_perm. Root half: split in staging.
template<int COUT, bool L1>
__global__ void __launch_bounds__(256) k_gemm_wm(const float* __restrict__ xin,
                                                 const unsigned short* __restrict__ Bimg,
                                                 const float* __restrict__ bias,
                                                 float* __restrict__ outp) {
    constexpr int BM = 64;
    constexpr int NP = COUT + 8;
    constexpr int AP = 136;
    constexpr int WN = COUT / 4;            // L1:32, L2:16
    constexpr int NT = WN / 16;             // L1:2,  L2:1
    constexpr int EW = WN + 4;
    extern __shared__ char smem[];
    __half* Ah = (__half*)smem;
    __half* Al = Ah + BM * AP;
    __half* Bs = Al + BM * AP;              // current half image: 128 x NP

    int tid = threadIdx.x, wid = tid >> 5, lane = tid & 31;
    int wm = wid & 1, wn = wid >> 1;
    int rowBase = blockIdx.x * BM;

    wmma::fragment<wmma::accumulator, 16, 16, 16, float> acc[2][NT];
#pragma unroll
    for (int i = 0; i < 2; i++)
#pragma unroll
        for (int j = 0; j < NT; j++) wmma::fill_fragment(acc[i][j], 0.0f);

    const float* rootSrc = L1 ? xin : g_h;
    int r = tid >> 2, kq = (tid & 3) << 5;
    int grow = rowBase + r;

    for (int half = 0; half < 2; half++) {
        // async B copy -- overlaps A staging
        {
            const char* src = (const char*)(Bimg + (size_t)half * 128 * NP);
            const int n4 = 128 * NP * 2 / 16;
            for (int i = tid; i < n4; i += 256)
                __pipeline_memcpy_async((char*)Bs + i * 16, src + i * 16, 16);
            __pipeline_commit();
        }
        unsigned short* ahp = (unsigned short*)Ah + (size_t)r * AP + kq;
        unsigned short* alp = (unsigned short*)Al + (size_t)r * AP + kq;
        if (half == 0) {
            // aggr half: pre-packed, unpack with byte_perm
            const uint4* pv = (grow < NN) ? (const uint4*)(g_aggrP + (size_t)grow * 128 + kq) : nullptr;
#pragma unroll
            for (int i = 0; i < 8; i++) {
                uint4 p = pv ? pv[i] : make_uint4(0u, 0u, 0u, 0u);
                uint32_t ah0 = __byte_perm(p.x, p.y, 0x5410);   // (h0, h1)
                uint32_t al0 = __byte_perm(p.x, p.y, 0x7632);   // (l0, l1)
                uint32_t ah1 = __byte_perm(p.z, p.w, 0x5410);
                uint32_t al1 = __byte_perm(p.z, p.w, 0x7632);
                *(uint2*)(ahp + i * 4) = make_uint2(ah0, ah1);
                *(uint2*)(alp + i * 4) = make_uint2(al0, al1);
            }
        } else {
            // root half: fp32 -> split in staging
            const float4* srcv = (grow < NN) ? (const float4*)(rootSrc + (size_t)grow * 128 + kq) : nullptr;
#pragma unroll
            for (int i = 0; i < 8; i++) {
                float4 v = srcv ? srcv[i] : make_float4(0.f, 0.f, 0.f, 0.f);
                uint32_t h0, l0, h1, l1;
                split2h(v.x, v.y, h0, l0);
                split2h(v.z, v.w, h1, l1);
                *(uint2*)(ahp + i * 4) = make_uint2(h0, h1);
                *(uint2*)(alp + i * 4) = make_uint2(l0, l1);
            }
        }
        __pipeline_wait_prior(0);
        __syncthreads();

#pragma unroll
        for (int ks = 0; ks < 8; ks++) {
            int k0 = ks * 16;
            wmma::fragment<wmma::matrix_a, 16, 16, 16, __half, wmma::row_major> fa_h[2], fa_l[2];
#pragma unroll
            for (int mt = 0; mt < 2; mt++) {
                wmma::load_matrix_sync(fa_h[mt], Ah + (size_t)(wm * 32 + mt * 16) * AP + k0, AP);
                wmma::load_matrix_sync(fa_l[mt], Al + (size_t)(wm * 32 + mt * 16) * AP + k0, AP);
            }
#pragma unroll
            for (int nt = 0; nt < NT; nt++) {
                wmma::fragment<wmma::matrix_b, 16, 16, 16, __half, wmma::row_major> fb;
                wmma::load_matrix_sync(fb, Bs + (size_t)k0 * NP + wn * WN + nt * 16, NP);
#pragma unroll
                for (int mt = 0; mt < 2; mt++) wmma::mma_sync(acc[mt][nt], fa_h[mt], fb, acc[mt][nt]);
#pragma unroll
                for (int mt = 0; mt < 2; mt++) wmma::mma_sync(acc[mt][nt], fa_l[mt], fb, acc[mt][nt]);
            }
        }
        __syncthreads();
    }

    // ---- epilogue: bounce fragments through smem, fuse bias+ReLU ----
    float* bw = (float*)Ah + (size_t)wid * 32 * EW;
#pragma unroll
    for (int mt = 0; mt < 2; mt++)
#pragma unroll
        for (int nt = 0; nt < NT; nt++)
            wmma::store_matrix_sync(bw + mt * 16 * EW + nt * 16, acc[mt][nt], EW, wmma::mem_row_major);
    __syncwarp();

    int orow = rowBase + wm * 32 + lane;
    float* out = L1 ? g_h : outp;
    if (orow < NN) {
        float* op = out + (size_t)orow * COUT + wn * WN;
        const float* br = bw + (size_t)lane * EW;
#pragma unroll
        for (int c = 0; c < WN; c += 4) {
            float4 v = make_float4(br[c], br[c + 1], br[c + 2], br[c + 3]);
            v.x += bias[wn * WN + c + 0];
            v.y += bias[wn * WN + c + 1];
            v.z += bias[wn * WN + c + 2];
            v.w += bias[wn * WN + c + 3];
            if (L1) {
                v.x = fmaxf(v.x, 0.f); v.y = fmaxf(v.y, 0.f);
                v.z = fmaxf(v.z, 0.f); v.w = fmaxf(v.w, 0.f);
            }
            *(float4*)(op + c) = v;
        }
    }
}

extern "C" void kernel_launch(void* const* d_in, const int* in_sizes, int n_in,
                              void* d_out, int out_size) {
    const float* x   = (const float*)d_in[0];
    const int*   ei  = (const int*)d_in[1];
    const float* W1l = (const float*)d_in[2];
    const float* b1  = (const float*)d_in[3];
    const float* W1r = (const float*)d_in[4];
    const float* W2l = (const float*)d_in[5];
    const float* b2  = (const float*)d_in[6];
    const float* W2r = (const float*)d_in[7];
    float*       out = (float*)d_out;

    const int* esrc = ei;
    const int* edst = ei + NE;

    const int edgeBlocks = (NE + 255) / 256;
    const int aggrBlocks = (NN * 32 + 255) / 256;
    const int gemmBlocks = (NN + 63) / 64;              // 1563

    // dynamic SMEM: A(2 x 64 x 136) + B(128 x NP), fp16
    const int SMEM1 = (2 * 64 * 136 + 128 * 136) * 2;   // 69,632 -> 3 CTAs/SM
    const int SMEM2 = (2 * 64 * 136 + 128 * 72) * 2;    // 53,248 -> 4 CTAs/SM
    cudaFuncSetAttribute(k_gemm_wm<128, true>, cudaFuncAttributeMaxDynamicSharedMemorySize, SMEM1);
    cudaFuncSetAttribute(k_gemm_wm<64, false>, cudaFuncAttributeMaxDynamicSharedMemorySize, SMEM2);

    unsigned short *bimg1, *bimg2;
    cudaGetSymbolAddress((void**)&bimg1, g_Bimg1);
    cudaGetSymbolAddress((void**)&bimg2, g_Bimg2);

    // CSR build: count (also resets lookback flags) -> one-pass scan -> fill
    k_count<<<edgeBlocks, 256>>>(edst);                                        // 1
    k_scanOP<<<NBLK, SCAN_B>>>();                                              // 2
    k_fill<<<edgeBlocks, 256>>>(esrc, edst);                                   // 3

    // Layer 1 aggregation -- launch slot 4 (ncu sample)
    k_aggr<false><<<aggrBlocks, 256>>>(x);                                     // 4

    // weight prep
    k_prepB<128><<<(2 * 128 * 128 + 255) / 256, 256>>>(W1l, W1r, bimg1);       // 5
    k_prepB<64><<<(2 * 128 * 64 + 255) / 256, 256>>>(W2l, W2r, bimg2);         // 6

    // Layer 1 GEMM, layer 2
    k_gemm_wm<128, true><<<gemmBlocks, 256, SMEM1>>>(x, bimg1, b1, nullptr);   // 7
    k_aggr<true><<<aggrBlocks, 256>>>(nullptr);                                 // 8
    k_gemm_wm<64, false><<<gemmBlocks, 256, SMEM2>>>(nullptr, bimg2, b2, out);  // 9
}